// round 1
// baseline (speedup 1.0000x reference)
#include <cuda_runtime.h>
#include <cstddef>

// Fused concat-linear: y[m, o] = sum_k x[m,k] * W[o,k] + b[o]
// Output reordered into 3 concatenated segments:
//   out[seg*M*H + m*H + (o - seg*H)]  with H = N/3 = 4096.
//
// Round-1 baseline: fp32 SIMT tiled GEMM (guaranteed-accurate), 128x128x16,
// double-buffered shared memory, 8x8 per-thread microtile, float4 everywhere.

static constexpr int BM = 128;
static constexpr int BN = 128;
static constexpr int BK = 16;
static constexpr int TM = 8;
static constexpr int TN = 8;
static constexpr int THREADS = 256;   // (BM/TM) * (BN/TN)
static constexpr int PAD = 4;

__global__ __launch_bounds__(THREADS, 2)
void concat_linear_gemm(const float* __restrict__ A,   // [M, K]
                        const float* __restrict__ B,   // [N, K]
                        const float* __restrict__ bias,// [N]
                        float* __restrict__ out,       // 3 x [M, H]
                        int M, int N, int K, int H)
{
    __shared__ float As[2][BK][BM + PAD];
    __shared__ float Bs[2][BK][BN + PAD];

    const int tid = threadIdx.x;
    const int tx  = tid & 15;   // N direction (0..15)
    const int ty  = tid >> 4;   // M direction (0..15)

    const int m0 = blockIdx.y * BM;
    const int n0 = blockIdx.x * BN;

    // Global-load mapping: 512 float4 per operand tile, 2 per thread.
    const int lrow = tid >> 2;    // 0..63  (row within tile, second load = +64)
    const int lqd  = tid & 3;     // which float4 along the 16-wide K slab

    const float* Aptr = A + (size_t)m0 * K;
    const float* Bptr = B + (size_t)n0 * K;

    float acc[TM][TN];
    #pragma unroll
    for (int i = 0; i < TM; ++i)
        #pragma unroll
        for (int j = 0; j < TN; ++j) acc[i][j] = 0.0f;

    const int KT = K / BK;

    // ---- load tile 0 straight into smem buffer 0 ----
    {
        const int kbase = lqd * 4;
        float4 a0 = *reinterpret_cast<const float4*>(Aptr + (size_t)lrow * K + kbase);
        float4 a1 = *reinterpret_cast<const float4*>(Aptr + (size_t)(lrow + 64) * K + kbase);
        float4 b0 = *reinterpret_cast<const float4*>(Bptr + (size_t)lrow * K + kbase);
        float4 b1 = *reinterpret_cast<const float4*>(Bptr + (size_t)(lrow + 64) * K + kbase);
        As[0][lqd * 4 + 0][lrow] = a0.x;  As[0][lqd * 4 + 1][lrow] = a0.y;
        As[0][lqd * 4 + 2][lrow] = a0.z;  As[0][lqd * 4 + 3][lrow] = a0.w;
        As[0][lqd * 4 + 0][lrow + 64] = a1.x;  As[0][lqd * 4 + 1][lrow + 64] = a1.y;
        As[0][lqd * 4 + 2][lrow + 64] = a1.z;  As[0][lqd * 4 + 3][lrow + 64] = a1.w;
        Bs[0][lqd * 4 + 0][lrow] = b0.x;  Bs[0][lqd * 4 + 1][lrow] = b0.y;
        Bs[0][lqd * 4 + 2][lrow] = b0.z;  Bs[0][lqd * 4 + 3][lrow] = b0.w;
        Bs[0][lqd * 4 + 0][lrow + 64] = b1.x;  Bs[0][lqd * 4 + 1][lrow + 64] = b1.y;
        Bs[0][lqd * 4 + 2][lrow + 64] = b1.z;  Bs[0][lqd * 4 + 3][lrow + 64] = b1.w;
    }
    __syncthreads();

    int buf = 0;
    for (int kt = 0; kt < KT; ++kt) {
        // ---- prefetch next K-slab into registers ----
        float4 pa0, pa1, pb0, pb1;
        const bool have_next = (kt + 1 < KT);
        if (have_next) {
            const int kbase = (kt + 1) * BK + lqd * 4;
            pa0 = *reinterpret_cast<const float4*>(Aptr + (size_t)lrow * K + kbase);
            pa1 = *reinterpret_cast<const float4*>(Aptr + (size_t)(lrow + 64) * K + kbase);
            pb0 = *reinterpret_cast<const float4*>(Bptr + (size_t)lrow * K + kbase);
            pb1 = *reinterpret_cast<const float4*>(Bptr + (size_t)(lrow + 64) * K + kbase);
        }

        // ---- compute on current buffer ----
        #pragma unroll
        for (int k = 0; k < BK; ++k) {
            float4 a0 = *reinterpret_cast<const float4*>(&As[buf][k][ty * TM]);
            float4 a1 = *reinterpret_cast<const float4*>(&As[buf][k][ty * TM + 4]);
            float4 b0 = *reinterpret_cast<const float4*>(&Bs[buf][k][tx * TN]);
            float4 b1 = *reinterpret_cast<const float4*>(&Bs[buf][k][tx * TN + 4]);
            const float ar[TM] = {a0.x, a0.y, a0.z, a0.w, a1.x, a1.y, a1.z, a1.w};
            const float br[TN] = {b0.x, b0.y, b0.z, b0.w, b1.x, b1.y, b1.z, b1.w};
            #pragma unroll
            for (int i = 0; i < TM; ++i)
                #pragma unroll
                for (int j = 0; j < TN; ++j)
                    acc[i][j] += ar[i] * br[j];
        }

        // ---- commit prefetched slab into the other buffer ----
        if (have_next) {
            const int nb = buf ^ 1;
            As[nb][lqd * 4 + 0][lrow] = pa0.x;  As[nb][lqd * 4 + 1][lrow] = pa0.y;
            As[nb][lqd * 4 + 2][lrow] = pa0.z;  As[nb][lqd * 4 + 3][lrow] = pa0.w;
            As[nb][lqd * 4 + 0][lrow + 64] = pa1.x;  As[nb][lqd * 4 + 1][lrow + 64] = pa1.y;
            As[nb][lqd * 4 + 2][lrow + 64] = pa1.z;  As[nb][lqd * 4 + 3][lrow + 64] = pa1.w;
            Bs[nb][lqd * 4 + 0][lrow] = pb0.x;  Bs[nb][lqd * 4 + 1][lrow] = pb0.y;
            Bs[nb][lqd * 4 + 2][lrow] = pb0.z;  Bs[nb][lqd * 4 + 3][lrow] = pb0.w;
            Bs[nb][lqd * 4 + 0][lrow + 64] = pb1.x;  Bs[nb][lqd * 4 + 1][lrow + 64] = pb1.y;
            Bs[nb][lqd * 4 + 2][lrow + 64] = pb1.z;  Bs[nb][lqd * 4 + 3][lrow + 64] = pb1.w;
            __syncthreads();
            buf = nb;
        }
    }

    // ---- epilogue: add bias, write with concat-segment mapping ----
    // One 128-wide N tile never straddles a 4096 segment boundary.
    const int seg  = n0 / H;
    const int nloc = n0 % H;
    float* outseg = out + (size_t)seg * (size_t)M * (size_t)H;

    float bv[TN];
    #pragma unroll
    for (int j = 0; j < TN; ++j)
        bv[j] = bias[n0 + tx * TN + j];

    #pragma unroll
    for (int i = 0; i < TM; ++i) {
        const int gm = m0 + ty * TM + i;
        float* op = outseg + (size_t)gm * H + nloc + tx * TN;
        float4 v0, v1;
        v0.x = acc[i][0] + bv[0];  v0.y = acc[i][1] + bv[1];
        v0.z = acc[i][2] + bv[2];  v0.w = acc[i][3] + bv[3];
        v1.x = acc[i][4] + bv[4];  v1.y = acc[i][5] + bv[5];
        v1.z = acc[i][6] + bv[6];  v1.w = acc[i][7] + bv[7];
        *reinterpret_cast<float4*>(op)     = v0;
        *reinterpret_cast<float4*>(op + 4) = v1;
    }
}

extern "C" void kernel_launch(void* const* d_in, const int* in_sizes, int n_in,
                              void* d_out, int out_size)
{
    const float* x = (const float*)d_in[0];   // [4, 2048, 4096] -> [M, K]
    const float* W = (const float*)d_in[1];   // [12288, 4096]   -> [N, K]
    const float* b = (const float*)d_in[2];   // [12288]
    float* out = (float*)d_out;

    const int N = in_sizes[2];            // 12288
    const int K = in_sizes[1] / N;        // 4096
    const int M = in_sizes[0] / K;        // 8192
    const int H = N / 3;                  // 4096

    dim3 grid(N / BN, M / BM);            // (96, 64)
    concat_linear_gemm<<<grid, THREADS>>>(x, W, b, out, M, N, K, H);
}

// round 3
// speedup vs baseline: 3.5603x; 3.5603x over previous
#include <cuda_runtime.h>
#include <cstdint>
#include <cstddef>

// ---------------------------------------------------------------------------
// Fused concat-linear via single-pass TF32 mma.sync (sm_103 non-'a' target:
// tcgen05 unavailable in this toolchain; mma.sync is the tensor path).
//   y[m,o] = sum_k x[m,k] * W[o,k] + b[o];  M=8192, N=12288, K=4096
//   out = 3 segments of H=4096 along o: out[seg][m][o - seg*H]
// TF32 rel-err ~2e-4 (budget 1e-3). fp32 accumulate in mma.sync.
// ---------------------------------------------------------------------------

#define MDIM 8192
#define NDIM 12288
#define KDIM 4096
#define HDIM 4096

static constexpr int BM = 128;
static constexpr int BN = 128;
static constexpr int BK = 32;
static constexpr int STAGES = 3;
static constexpr int THREADS = 256;

static constexpr int TS = 36;                    // smem row stride in floats (pad 32->36)
static constexpr int TILE_FLOATS  = 128 * TS;    // one operand tile
static constexpr int STAGE_FLOATS = 2 * TILE_FLOATS;
static constexpr int SMEM_BYTES   = STAGES * STAGE_FLOATS * 4;   // 110,592

static constexpr int TILES_M = MDIM / BM;        // 64
static constexpr int TILES_N = NDIM / BN;        // 96
static constexpr int GROUP_M = 16;               // band height (L2 blocking)

__device__ __forceinline__ uint32_t smem_u32(const void* p) {
    return (uint32_t)__cvta_generic_to_shared(p);
}
__device__ __forceinline__ void cp16(uint32_t dst, const void* src) {
    asm volatile("cp.async.cg.shared.global [%0], [%1], 16;" :: "r"(dst), "l"(src));
}
__device__ __forceinline__ uint32_t f2tf32(float x) {
    uint32_t r;
    asm("cvt.rna.tf32.f32 %0, %1;" : "=r"(r) : "f"(x));
    return r;
}
__device__ __forceinline__ void mma_tf32(float* c, const uint32_t* a, const uint32_t* b) {
    asm volatile(
        "mma.sync.aligned.m16n8k8.row.col.f32.tf32.tf32.f32 "
        "{%0,%1,%2,%3}, {%4,%5,%6,%7}, {%8,%9}, {%0,%1,%2,%3};"
        : "+f"(c[0]), "+f"(c[1]), "+f"(c[2]), "+f"(c[3])
        : "r"(a[0]), "r"(a[1]), "r"(a[2]), "r"(a[3]), "r"(b[0]), "r"(b[1]));
}

__global__ __launch_bounds__(THREADS, 2)
void gemm_tf32(const float* __restrict__ A,     // [M,K]
               const float* __restrict__ B,     // [N,K]
               const float* __restrict__ bias,  // [N]
               float* __restrict__ out)         // 3 x [M,H]
{
    extern __shared__ float smem[];
    const uint32_t sbase = smem_u32(smem);

    const int tid  = threadIdx.x;
    const int wid  = tid >> 5;
    const int lane = tid & 31;
    const int gid  = lane >> 2;      // 0..7
    const int tig  = lane & 3;       // 0..3
    const int warp_m = wid & 1;      // 2 warps along M (64 rows each)
    const int warp_n = wid >> 1;     // 4 warps along N (32 cols each)

    // ---- tile swizzle: M-bands of GROUP_M, sweep N within band ----
    const int bid  = blockIdx.x;
    const int band = bid / (GROUP_M * TILES_N);
    const int rem  = bid % (GROUP_M * TILES_N);
    const int mt   = band * GROUP_M + (rem % GROUP_M);
    const int nt   = rem / GROUP_M;
    const int m0 = mt * BM;
    const int n0 = nt * BN;

    // ---- global load mapping: 8 cp.async x 16B per thread per stage ----
    const int lrow = tid >> 3;                   // 0..31
    const int lc4  = tid & 7;                    // float4 index along K
    const float* Ag = A + (size_t)(m0 + lrow) * KDIM + lc4 * 4;
    const float* Bg = B + (size_t)(n0 + lrow) * KDIM + lc4 * 4;
    const uint32_t s_off = (uint32_t)(lrow * TS + lc4 * 4) * 4;

    float acc[4][4][4];
#pragma unroll
    for (int mi = 0; mi < 4; mi++)
#pragma unroll
        for (int ni = 0; ni < 4; ni++)
#pragma unroll
            for (int q = 0; q < 4; q++) acc[mi][ni][q] = 0.0f;

    const int KT = KDIM / BK;                    // 128

    // ---- prologue: fill STAGES-1 stages ----
#pragma unroll
    for (int s = 0; s < STAGES - 1; s++) {
        const uint32_t a_s = sbase + (uint32_t)(s * STAGE_FLOATS) * 4;
        const uint32_t b_s = a_s + TILE_FLOATS * 4;
        const size_t koff = (size_t)s * BK;
#pragma unroll
        for (int r = 0; r < 4; r++) {
            cp16(a_s + s_off + r * (32 * TS * 4), Ag + (size_t)(32 * r) * KDIM + koff);
            cp16(b_s + s_off + r * (32 * TS * 4), Bg + (size_t)(32 * r) * KDIM + koff);
        }
        asm volatile("cp.async.commit_group;" ::: "memory");
    }

    const int arow = warp_m * 64 + gid;
    const int brow = warp_n * 32 + gid;

    for (int kt = 0; kt < KT; kt++) {
        asm volatile("cp.async.wait_group %0;" :: "n"(STAGES - 2) : "memory");
        __syncthreads();

        // issue load for stage kt+STAGES-1 (slot reused from kt-1's compute)
        const int kin = kt + STAGES - 1;
        if (kin < KT) {
            const int s = kin % STAGES;
            const uint32_t a_s = sbase + (uint32_t)(s * STAGE_FLOATS) * 4;
            const uint32_t b_s = a_s + TILE_FLOATS * 4;
            const size_t koff = (size_t)kin * BK;
#pragma unroll
            for (int r = 0; r < 4; r++) {
                cp16(a_s + s_off + r * (32 * TS * 4), Ag + (size_t)(32 * r) * KDIM + koff);
                cp16(b_s + s_off + r * (32 * TS * 4), Bg + (size_t)(32 * r) * KDIM + koff);
            }
        }
        asm volatile("cp.async.commit_group;" ::: "memory");

        // ---- compute on stage kt%STAGES ----
        const float* as = smem + (kt % STAGES) * STAGE_FLOATS;
        const float* bs = as + TILE_FLOATS;
#pragma unroll
        for (int ks = 0; ks < 4; ks++) {
            const int k0 = ks * 8;
            uint32_t afr[4][4];
            uint32_t bfr[4][2];
#pragma unroll
            for (int mi = 0; mi < 4; mi++) {
                const float* ap = as + (arow + mi * 16) * TS + k0 + tig;
                afr[mi][0] = f2tf32(ap[0]);
                afr[mi][1] = f2tf32(ap[8 * TS]);
                afr[mi][2] = f2tf32(ap[4]);
                afr[mi][3] = f2tf32(ap[8 * TS + 4]);
            }
#pragma unroll
            for (int ni = 0; ni < 4; ni++) {
                const float* bp = bs + (brow + ni * 8) * TS + k0 + tig;
                bfr[ni][0] = f2tf32(bp[0]);
                bfr[ni][1] = f2tf32(bp[4]);
            }
#pragma unroll
            for (int mi = 0; mi < 4; mi++)
#pragma unroll
                for (int ni = 0; ni < 4; ni++)
                    mma_tf32(acc[mi][ni], afr[mi], bfr[ni]);
        }
    }

    // ---- epilogue: bias + segmented store ----
    const int seg  = n0 / HDIM;      // 128-wide N tile never straddles a segment
    const int nloc = n0 % HDIM;
    float* outseg = out + (size_t)seg * MDIM * HDIM;

#pragma unroll
    for (int ni = 0; ni < 4; ni++) {
        const int gn = n0 + warp_n * 32 + ni * 8 + 2 * tig;
        const float b0 = __ldg(bias + gn);
        const float b1 = __ldg(bias + gn + 1);
        const int cn = nloc + warp_n * 32 + ni * 8 + 2 * tig;
#pragma unroll
        for (int mi = 0; mi < 4; mi++) {
            const int gm = m0 + warp_m * 64 + mi * 16 + gid;
            float2 v0, v1;
            v0.x = acc[mi][ni][0] + b0;  v0.y = acc[mi][ni][1] + b1;
            v1.x = acc[mi][ni][2] + b0;  v1.y = acc[mi][ni][3] + b1;
            *reinterpret_cast<float2*>(outseg + (size_t)gm * HDIM + cn)       = v0;
            *reinterpret_cast<float2*>(outseg + (size_t)(gm + 8) * HDIM + cn) = v1;
        }
    }
}

extern "C" void kernel_launch(void* const* d_in, const int* in_sizes, int n_in,
                              void* d_out, int out_size)
{
    const float* x = (const float*)d_in[0];
    const float* W = (const float*)d_in[1];
    const float* b = (const float*)d_in[2];
    float* out = (float*)d_out;

    cudaFuncSetAttribute(gemm_tf32, cudaFuncAttributeMaxDynamicSharedMemorySize, SMEM_BYTES);
    gemm_tf32<<<TILES_M * TILES_N, THREADS, SMEM_BYTES>>>(x, W, b, out);
}

// round 4
// speedup vs baseline: 4.2389x; 1.1906x over previous
#include <cuda_runtime.h>
#include <cstdint>
#include <cstddef>

// ---------------------------------------------------------------------------
// Fused concat-linear, single-pass TF32 mma.sync, fragment-packed operands.
//   y[m,o] = sum_k x[m,k] W[o,k] + b[o];  M=8192 N=12288 K=4096
//   out = 3 segments of H=4096 along o.
// Pack kernels pre-round to TF32 (cvt.rna) and lay operands out so the GEMM
// mainloop fetches register fragments with single LDS.128s and issues no CVTs.
// ---------------------------------------------------------------------------

#define MDIM 8192
#define NDIM 12288
#define KDIM 4096
#define HDIM 4096

static constexpr int BM = 128;
static constexpr int BN = 128;
static constexpr int BK = 32;
static constexpr int STAGES = 3;
static constexpr int THREADS = 256;

static constexpr int MT16 = MDIM / 16;        // 512
static constexpr int NT16 = NDIM / 16;        // 768
static constexpr int KC32 = KDIM / 32;        // 128

// packed scratch: [kc32][t16][kc8(4)][lane(32)][q(4)] words
__device__ uint32_t g_Apack[(size_t)KC32 * MT16 * 512];   // 134 MB
__device__ uint32_t g_Bpack[(size_t)KC32 * NT16 * 512];   // 201 MB

static constexpr int STAGE_WORDS = 8192;                   // 16KB A + 16KB B
static constexpr int SMEM_BYTES  = STAGES * STAGE_WORDS * 4;   // 98304

static constexpr int TILES_M = MDIM / BM;     // 64
static constexpr int TILES_N = NDIM / BN;     // 96
static constexpr int GROUP_M = 16;

__device__ __forceinline__ uint32_t smem_u32(const void* p) {
    return (uint32_t)__cvta_generic_to_shared(p);
}
__device__ __forceinline__ void cp16(uint32_t dst, const void* src) {
    asm volatile("cp.async.cg.shared.global [%0], [%1], 16;" :: "r"(dst), "l"(src));
}
__device__ __forceinline__ uint32_t f2tf32(float x) {
    uint32_t r;
    asm("cvt.rna.tf32.f32 %0, %1;" : "=r"(r) : "f"(x));
    return r;
}
__device__ __forceinline__ void mma_tf32(float* c, const uint32_t* a, const uint32_t* b) {
    asm volatile(
        "mma.sync.aligned.m16n8k8.row.col.f32.tf32.tf32.f32 "
        "{%0,%1,%2,%3}, {%4,%5,%6,%7}, {%8,%9}, {%0,%1,%2,%3};"
        : "+f"(c[0]), "+f"(c[1]), "+f"(c[2]), "+f"(c[3])
        : "r"(a[0]), "r"(a[1]), "r"(a[2]), "r"(a[3]), "r"(b[0]), "r"(b[1]));
}

// ---------------- pack kernels ----------------
// unit idx = ((kc32*T16 + t16)*4 + kc8)*32 + lane ; each unit stores 4 words:
//   q0 = S[t16*16+gid    ][k+tig], q1 = S[t16*16+8+gid][k+tig],
//   q2 = S[t16*16+gid    ][k+4+tig], q3 = S[t16*16+8+gid][k+4+tig]
__global__ __launch_bounds__(256)
void pack_a(const float* __restrict__ src, uint32_t* __restrict__ dst) {
    const uint32_t idx = blockIdx.x * 256u + threadIdx.x;     // < 8388608
    const int lane = idx & 31, kc8 = (idx >> 5) & 3;
    const int t16 = (idx >> 7) & 511, kc32 = idx >> 16;
    const int gid = lane >> 2, tig = lane & 3;
    const size_t rbase = (size_t)(t16 * 16 + gid) * KDIM + kc32 * 32 + kc8 * 8 + tig;
    uint4 w;
    w.x = f2tf32(src[rbase]);
    w.y = f2tf32(src[rbase + 8 * (size_t)KDIM]);
    w.z = f2tf32(src[rbase + 4]);
    w.w = f2tf32(src[rbase + 8 * (size_t)KDIM + 4]);
    reinterpret_cast<uint4*>(dst)[idx] = w;
}
__global__ __launch_bounds__(256)
void pack_b(const float* __restrict__ src, uint32_t* __restrict__ dst) {
    const uint32_t idx = blockIdx.x * 256u + threadIdx.x;     // < 12582912
    const int lane = idx & 31, kc8 = (idx >> 5) & 3;
    const int kc32 = idx / 98304;                 // 768*4*32 units per kc32
    const int t16  = (idx % 98304) >> 7;
    const int gid = lane >> 2, tig = lane & 3;
    const size_t rbase = (size_t)(t16 * 16 + gid) * KDIM + kc32 * 32 + kc8 * 8 + tig;
    uint4 w;
    w.x = f2tf32(src[rbase]);
    w.y = f2tf32(src[rbase + 8 * (size_t)KDIM]);
    w.z = f2tf32(src[rbase + 4]);
    w.w = f2tf32(src[rbase + 8 * (size_t)KDIM + 4]);
    reinterpret_cast<uint4*>(dst)[idx] = w;
}

// ---------------- GEMM ----------------
__global__ __launch_bounds__(THREADS, 2)
void gemm_tf32(const uint32_t* __restrict__ Apack,
               const uint32_t* __restrict__ Bpack,
               const float* __restrict__ bias,
               float* __restrict__ out)
{
    extern __shared__ uint32_t smemu[];
    const uint32_t sbase = smem_u32(smemu);

    const int tid  = threadIdx.x;
    const int wid  = tid >> 5;
    const int lane = tid & 31;
    const int gid  = lane >> 2;
    const int tig  = lane & 3;
    const int warp_m = wid & 1;     // 64 rows
    const int warp_n = wid >> 1;    // 32 cols

    const int bid  = blockIdx.x;
    const int band = bid / (GROUP_M * TILES_N);
    const int rem  = bid % (GROUP_M * TILES_N);
    const int mt   = band * GROUP_M + (rem % GROUP_M);
    const int nt   = rem / GROUP_M;
    const int m0 = mt * BM;
    const int n0 = nt * BN;

    // stage sources: contiguous 16KB chunks in packed gmem
    const uint32_t* Asrc = Apack + ((size_t)0 * MT16 + (m0 >> 4)) * 512 + tid * 4;
    const uint32_t* Bsrc = Bpack + ((size_t)0 * NT16 + (n0 >> 4)) * 512 + tid * 4;
    const size_t AstageStep = (size_t)MT16 * 512;   // words per kc32
    const size_t BstageStep = (size_t)NT16 * 512;

    float acc[4][4][4];
#pragma unroll
    for (int mi = 0; mi < 4; mi++)
#pragma unroll
        for (int ni = 0; ni < 4; ni++)
#pragma unroll
            for (int q = 0; q < 4; q++) acc[mi][ni][q] = 0.0f;

    const int KT = KDIM / BK;    // 128

#pragma unroll
    for (int s = 0; s < STAGES - 1; s++) {
        const uint32_t a_s = sbase + (uint32_t)(s * STAGE_WORDS) * 4;
        const uint32_t b_s = a_s + 4096 * 4;
#pragma unroll
        for (int i = 0; i < 4; i++) {
            cp16(a_s + tid * 16 + i * 4096, Asrc + (size_t)s * AstageStep + i * 1024);
            cp16(b_s + tid * 16 + i * 4096, Bsrc + (size_t)s * BstageStep + i * 1024);
        }
        asm volatile("cp.async.commit_group;" ::: "memory");
    }

    for (int kt = 0; kt < KT; kt++) {
        asm volatile("cp.async.wait_group %0;" :: "n"(STAGES - 2) : "memory");
        __syncthreads();

        const int kin = kt + STAGES - 1;
        if (kin < KT) {
            const int s = kin % STAGES;
            const uint32_t a_s = sbase + (uint32_t)(s * STAGE_WORDS) * 4;
            const uint32_t b_s = a_s + 4096 * 4;
#pragma unroll
            for (int i = 0; i < 4; i++) {
                cp16(a_s + tid * 16 + i * 4096, Asrc + (size_t)kin * AstageStep + i * 1024);
                cp16(b_s + tid * 16 + i * 4096, Bsrc + (size_t)kin * BstageStep + i * 1024);
            }
        }
        asm volatile("cp.async.commit_group;" ::: "memory");

        // smem stage layout: A = [mtile(8)][kc8(4)][lane(32)][q(4)], B same with ntiles
        const uint32_t* as = smemu + (kt % STAGES) * STAGE_WORDS;
        const uint32_t* bs = as + 4096;
#pragma unroll
        for (int ks = 0; ks < 4; ks++) {
            uint4 af[4], bf[2];
#pragma unroll
            for (int mi = 0; mi < 4; mi++)
                af[mi] = *reinterpret_cast<const uint4*>(
                    as + (((warp_m * 4 + mi) * 4 + ks) << 7) + lane * 4);
#pragma unroll
            for (int nj = 0; nj < 2; nj++)
                bf[nj] = *reinterpret_cast<const uint4*>(
                    bs + (((warp_n * 2 + nj) * 4 + ks) << 7) + lane * 4);

            uint32_t bfr[4][2] = {
                {bf[0].x, bf[0].z}, {bf[0].y, bf[0].w},
                {bf[1].x, bf[1].z}, {bf[1].y, bf[1].w}};
#pragma unroll
            for (int mi = 0; mi < 4; mi++) {
                const uint32_t afr[4] = {af[mi].x, af[mi].y, af[mi].z, af[mi].w};
#pragma unroll
                for (int ni = 0; ni < 4; ni++)
                    mma_tf32(acc[mi][ni], afr, bfr[ni]);
            }
        }
    }

    // ---- epilogue ----
    const int seg  = n0 / HDIM;
    const int nloc = n0 % HDIM;
    float* outseg = out + (size_t)seg * MDIM * HDIM;

#pragma unroll
    for (int ni = 0; ni < 4; ni++) {
        const int gn = n0 + warp_n * 32 + ni * 8 + 2 * tig;
        const float b0 = __ldg(bias + gn);
        const float b1 = __ldg(bias + gn + 1);
        const int cn = nloc + warp_n * 32 + ni * 8 + 2 * tig;
#pragma unroll
        for (int mi = 0; mi < 4; mi++) {
            const int gm = m0 + warp_m * 64 + mi * 16 + gid;
            float2 v0, v1;
            v0.x = acc[mi][ni][0] + b0;  v0.y = acc[mi][ni][1] + b1;
            v1.x = acc[mi][ni][2] + b0;  v1.y = acc[mi][ni][3] + b1;
            *reinterpret_cast<float2*>(outseg + (size_t)gm * HDIM + cn)       = v0;
            *reinterpret_cast<float2*>(outseg + (size_t)(gm + 8) * HDIM + cn) = v1;
        }
    }
}

extern "C" void kernel_launch(void* const* d_in, const int* in_sizes, int n_in,
                              void* d_out, int out_size)
{
    const float* x = (const float*)d_in[0];
    const float* W = (const float*)d_in[1];
    const float* b = (const float*)d_in[2];
    float* out = (float*)d_out;

    void *ap, *bp;
    cudaGetSymbolAddress(&ap, g_Apack);
    cudaGetSymbolAddress(&bp, g_Bpack);

    pack_a<<<32768, 256>>>(x, (uint32_t*)ap);
    pack_b<<<49152, 256>>>(W, (uint32_t*)bp);

    cudaFuncSetAttribute(gemm_tf32, cudaFuncAttributeMaxDynamicSharedMemorySize, SMEM_BYTES);
    gemm_tf32<<<TILES_M * TILES_N, THREADS, SMEM_BYTES>>>(
        (const uint32_t*)ap, (const uint32_t*)bp, b, out);
}

// round 5
// speedup vs baseline: 4.3200x; 1.0191x over previous
#include <cuda_runtime.h>
#include <cstdint>
#include <cstddef>

// ---------------------------------------------------------------------------
// Fused concat-linear, single-pass TF32 mma.sync, fragment-packed operands.
// Round 5: 64x64 warp tiles (2x2 warps, 128 threads) -> per-MMA smem traffic
// drops 1.5x, moving the bottleneck from the smem crossbar to the tensor pipe.
// ---------------------------------------------------------------------------

#define MDIM 8192
#define NDIM 12288
#define KDIM 4096
#define HDIM 4096

static constexpr int STAGES = 3;
static constexpr int THREADS = 128;

static constexpr int MT16 = MDIM / 16;        // 512
static constexpr int NT16 = NDIM / 16;        // 768
static constexpr int KC32 = KDIM / 32;        // 128

// packed scratch: [kc32][t16][kc8(4)][lane(32)][q(4)] words
__device__ uint32_t g_Apack[(size_t)KC32 * MT16 * 512];
__device__ uint32_t g_Bpack[(size_t)KC32 * NT16 * 512];

static constexpr int STAGE_WORDS = 8192;                       // 16KB A + 16KB B
static constexpr int SMEM_BYTES  = STAGES * STAGE_WORDS * 4;   // 98304

static constexpr int TILES_M = MDIM / 128;    // 64
static constexpr int TILES_N = NDIM / 128;    // 96
static constexpr int GROUP_M = 16;

__device__ __forceinline__ uint32_t smem_u32(const void* p) {
    return (uint32_t)__cvta_generic_to_shared(p);
}
__device__ __forceinline__ void cp16(uint32_t dst, const void* src) {
    asm volatile("cp.async.cg.shared.global [%0], [%1], 16;" :: "r"(dst), "l"(src));
}
__device__ __forceinline__ uint32_t f2tf32(float x) {
    uint32_t r;
    asm("cvt.rna.tf32.f32 %0, %1;" : "=r"(r) : "f"(x));
    return r;
}
__device__ __forceinline__ void mma_tf32(float* c, const uint32_t* a, const uint32_t* b) {
    asm volatile(
        "mma.sync.aligned.m16n8k8.row.col.f32.tf32.tf32.f32 "
        "{%0,%1,%2,%3}, {%4,%5,%6,%7}, {%8,%9}, {%0,%1,%2,%3};"
        : "+f"(c[0]), "+f"(c[1]), "+f"(c[2]), "+f"(c[3])
        : "r"(a[0]), "r"(a[1]), "r"(a[2]), "r"(a[3]), "r"(b[0]), "r"(b[1]));
}

// ---------------- pack kernels (unchanged; validated R4) ----------------
__global__ __launch_bounds__(256)
void pack_a(const float* __restrict__ src, uint32_t* __restrict__ dst) {
    const uint32_t idx = blockIdx.x * 256u + threadIdx.x;
    const int lane = idx & 31, kc8 = (idx >> 5) & 3;
    const int t16 = (idx >> 7) & 511, kc32 = idx >> 16;
    const int gid = lane >> 2, tig = lane & 3;
    const size_t rbase = (size_t)(t16 * 16 + gid) * KDIM + kc32 * 32 + kc8 * 8 + tig;
    uint4 w;
    w.x = f2tf32(src[rbase]);
    w.y = f2tf32(src[rbase + 8 * (size_t)KDIM]);
    w.z = f2tf32(src[rbase + 4]);
    w.w = f2tf32(src[rbase + 8 * (size_t)KDIM + 4]);
    reinterpret_cast<uint4*>(dst)[idx] = w;
}
__global__ __launch_bounds__(256)
void pack_b(const float* __restrict__ src, uint32_t* __restrict__ dst) {
    const uint32_t idx = blockIdx.x * 256u + threadIdx.x;
    const int lane = idx & 31, kc8 = (idx >> 5) & 3;
    const int kc32 = idx / 98304;
    const int t16  = (idx % 98304) >> 7;
    const int gid = lane >> 2, tig = lane & 3;
    const size_t rbase = (size_t)(t16 * 16 + gid) * KDIM + kc32 * 32 + kc8 * 8 + tig;
    uint4 w;
    w.x = f2tf32(src[rbase]);
    w.y = f2tf32(src[rbase + 8 * (size_t)KDIM]);
    w.z = f2tf32(src[rbase + 4]);
    w.w = f2tf32(src[rbase + 8 * (size_t)KDIM + 4]);
    reinterpret_cast<uint4*>(dst)[idx] = w;
}

// ---------------- GEMM: 128x128 tile, 4 warps of 64x64 ----------------
__global__ __launch_bounds__(THREADS, 2)
void gemm_tf32(const uint32_t* __restrict__ Apack,
               const uint32_t* __restrict__ Bpack,
               const float* __restrict__ bias,
               float* __restrict__ out)
{
    extern __shared__ uint32_t smemu[];
    const uint32_t sbase = smem_u32(smemu);

    const int tid  = threadIdx.x;
    const int wid  = tid >> 5;
    const int lane = tid & 31;
    const int gid  = lane >> 2;
    const int tig  = lane & 3;
    const int warp_m = wid & 1;     // 64 rows
    const int warp_n = wid >> 1;    // 64 cols

    const int bid  = blockIdx.x;
    const int band = bid / (GROUP_M * TILES_N);
    const int rem  = bid % (GROUP_M * TILES_N);
    const int mt   = band * GROUP_M + (rem % GROUP_M);
    const int nt   = rem / GROUP_M;
    const int m0 = mt * 128;
    const int n0 = nt * 128;

    const uint32_t* Asrc = Apack + (size_t)(m0 >> 4) * 512 + tid * 4;
    const uint32_t* Bsrc = Bpack + (size_t)(n0 >> 4) * 512 + tid * 4;
    const size_t AstageStep = (size_t)MT16 * 512;
    const size_t BstageStep = (size_t)NT16 * 512;

    float acc[4][8][4];
#pragma unroll
    for (int mi = 0; mi < 4; mi++)
#pragma unroll
        for (int ni = 0; ni < 8; ni++)
#pragma unroll
            for (int q = 0; q < 4; q++) acc[mi][ni][q] = 0.0f;

    const int KT = KDIM / 32;    // 128

#pragma unroll
    for (int s = 0; s < STAGES - 1; s++) {
        const uint32_t a_s = sbase + (uint32_t)(s * STAGE_WORDS) * 4;
        const uint32_t b_s = a_s + 4096 * 4;
#pragma unroll
        for (int i = 0; i < 8; i++) {
            cp16(a_s + tid * 16 + i * 2048, Asrc + (size_t)s * AstageStep + i * 512);
            cp16(b_s + tid * 16 + i * 2048, Bsrc + (size_t)s * BstageStep + i * 512);
        }
        asm volatile("cp.async.commit_group;" ::: "memory");
    }

    for (int kt = 0; kt < KT; kt++) {
        asm volatile("cp.async.wait_group %0;" :: "n"(STAGES - 2) : "memory");
        __syncthreads();

        const int kin = kt + STAGES - 1;
        if (kin < KT) {
            const int s = kin % STAGES;
            const uint32_t a_s = sbase + (uint32_t)(s * STAGE_WORDS) * 4;
            const uint32_t b_s = a_s + 4096 * 4;
#pragma unroll
            for (int i = 0; i < 8; i++) {
                cp16(a_s + tid * 16 + i * 2048, Asrc + (size_t)kin * AstageStep + i * 512);
                cp16(b_s + tid * 16 + i * 2048, Bsrc + (size_t)kin * BstageStep + i * 512);
            }
        }
        asm volatile("cp.async.commit_group;" ::: "memory");

        // stage layout: A = [mtile(8)][ks(4)][lane(32)][q(4)], B likewise
        const uint32_t* as = smemu + (kt % STAGES) * STAGE_WORDS;
        const uint32_t* bs = as + 4096;
#pragma unroll
        for (int ks = 0; ks < 4; ks++) {
            uint4 af[4], bf[4];
#pragma unroll
            for (int mi = 0; mi < 4; mi++)
                af[mi] = *reinterpret_cast<const uint4*>(
                    as + (((warp_m * 4 + mi) * 4 + ks) << 7) + lane * 4);
#pragma unroll
            for (int nj = 0; nj < 4; nj++)
                bf[nj] = *reinterpret_cast<const uint4*>(
                    bs + (((warp_n * 4 + nj) * 4 + ks) << 7) + lane * 4);

#pragma unroll
            for (int mi = 0; mi < 4; mi++) {
                const uint32_t afr[4] = {af[mi].x, af[mi].y, af[mi].z, af[mi].w};
#pragma unroll
                for (int nj = 0; nj < 4; nj++) {
                    const uint32_t b0[2] = {bf[nj].x, bf[nj].z};
                    const uint32_t b1[2] = {bf[nj].y, bf[nj].w};
                    mma_tf32(acc[mi][nj * 2 + 0], afr, b0);
                    mma_tf32(acc[mi][nj * 2 + 1], afr, b1);
                }
            }
        }
    }

    // ---- epilogue: bias + segmented store ----
    const int seg  = n0 / HDIM;
    const int nloc = n0 % HDIM;
    float* outseg = out + (size_t)seg * MDIM * HDIM;

#pragma unroll
    for (int ni = 0; ni < 8; ni++) {
        const int gn = n0 + warp_n * 64 + ni * 8 + 2 * tig;
        const float b0 = __ldg(bias + gn);
        const float b1 = __ldg(bias + gn + 1);
        const int cn = nloc + warp_n * 64 + ni * 8 + 2 * tig;
#pragma unroll
        for (int mi = 0; mi < 4; mi++) {
            const int gm = m0 + warp_m * 64 + mi * 16 + gid;
            float2 v0, v1;
            v0.x = acc[mi][ni][0] + b0;  v0.y = acc[mi][ni][1] + b1;
            v1.x = acc[mi][ni][2] + b0;  v1.y = acc[mi][ni][3] + b1;
            *reinterpret_cast<float2*>(outseg + (size_t)gm * HDIM + cn)       = v0;
            *reinterpret_cast<float2*>(outseg + (size_t)(gm + 8) * HDIM + cn) = v1;
        }
    }
}

extern "C" void kernel_launch(void* const* d_in, const int* in_sizes, int n_in,
                              void* d_out, int out_size)
{
    const float* x = (const float*)d_in[0];
    const float* W = (const float*)d_in[1];
    const float* b = (const float*)d_in[2];
    float* out = (float*)d_out;

    void *ap, *bp;
    cudaGetSymbolAddress(&ap, g_Apack);
    cudaGetSymbolAddress(&bp, g_Bpack);

    pack_a<<<32768, 256>>>(x, (uint32_t*)ap);
    pack_b<<<49152, 256>>>(W, (uint32_t*)bp);

    cudaFuncSetAttribute(gemm_tf32, cudaFuncAttributeMaxDynamicSharedMemorySize, SMEM_BYTES);
    gemm_tf32<<<TILES_M * TILES_N, THREADS, SMEM_BYTES>>>(
        (const uint32_t*)ap, (const uint32_t*)bp, b, out);
}